// round 2
// baseline (speedup 1.0000x reference)
#include <cuda_runtime.h>
#include <cstdint>
#include <cstddef>

#define S_LEN 2048
#define B_DIM 64
#define I_DIM 512
#define H_DIM 512
#define G_DIM 2048  // 4*H

// ---------------- scratch (static device globals: allocation-free at launch) ----
__device__ __align__(16) float g_xw[(size_t)S_LEN * B_DIM * G_DIM];   // 1 GB: x@W + bias
__device__ __align__(16) float g_h[2][B_DIM * H_DIM];                 // double-buffered h
__device__ unsigned long long g_flags[128 * 16];        // per-CTA barrier flags, 128B apart

// ---------------- packed f32x2 helpers (2x fp32 FMA rate on Blackwell) ----------
__device__ __forceinline__ unsigned long long pk2(float lo, float hi) {
    unsigned long long r;
    asm("mov.b64 %0, {%1, %2};" : "=l"(r) : "f"(lo), "f"(hi));
    return r;
}
__device__ __forceinline__ void upk2(unsigned long long v, float& lo, float& hi) {
    asm("mov.b64 {%0, %1}, %2;" : "=f"(lo), "=f"(hi) : "l"(v));
}
__device__ __forceinline__ void ffma2(unsigned long long& d, unsigned long long a, unsigned long long b) {
    asm("fma.rn.f32x2 %0, %1, %2, %0;" : "+l"(d) : "l"(a), "l"(b));
}

__device__ __forceinline__ float sigmoidf_fast(float x) {
    return 1.0f / (1.0f + __expf(-x));
}

// =====================================================================
// Kernel 1: xW = x @ W + bias.  M=131072, N=2048, K=512, fp32.
// 128x128 block tile, KT=8, 256 threads, 8x8 per-thread tile, f32x2 FMAs.
// =====================================================================
__global__ __launch_bounds__(256, 2) void gemm_xw_kernel(
    const float* __restrict__ x, const float* __restrict__ W,
    const float* __restrict__ bias)
{
    __shared__ float As[8][128];   // transposed: As[k][m]
    __shared__ float Bs[8][128];   // Bs[k][n]

    const int t  = threadIdx.x;
    const int m0 = blockIdx.y * 128;
    const int n0 = blockIdx.x * 128;
    const int tx = t & 15;        // n-tile index
    const int ty = t >> 4;        // m-tile index

    const int arow = t >> 1, akc = (t & 1) * 4;   // A loader: row 0..127, k chunk 0/4
    const int brow = t >> 5, bnc = (t & 31) * 4;  // B loader: k row 0..7, n chunk

    unsigned long long acc[8][4];
    #pragma unroll
    for (int m = 0; m < 8; m++)
        #pragma unroll
        for (int n = 0; n < 4; n++) acc[m][n] = 0ULL;  // bit pattern {0.f,0.f}

    float4 av = *(const float4*)(x + (size_t)(m0 + arow) * I_DIM + akc);
    float4 bv = *(const float4*)(W + (size_t)brow * G_DIM + n0 + bnc);

    for (int kt = 0; kt < 64; kt++) {
        __syncthreads();
        As[akc + 0][arow] = av.x;
        As[akc + 1][arow] = av.y;
        As[akc + 2][arow] = av.z;
        As[akc + 3][arow] = av.w;
        *(float4*)&Bs[brow][bnc] = bv;
        __syncthreads();
        if (kt < 63) {
            av = *(const float4*)(x + (size_t)(m0 + arow) * I_DIM + (kt + 1) * 8 + akc);
            bv = *(const float4*)(W + (size_t)((kt + 1) * 8 + brow) * G_DIM + n0 + bnc);
        }
        #pragma unroll
        for (int kk = 0; kk < 8; kk++) {
            float4 a01 = *(const float4*)&As[kk][ty * 8];
            float4 a23 = *(const float4*)&As[kk][ty * 8 + 4];
            ulonglong2 b01 = *(const ulonglong2*)&Bs[kk][tx * 8];
            ulonglong2 b23 = *(const ulonglong2*)&Bs[kk][tx * 8 + 4];
            float am[8] = {a01.x, a01.y, a01.z, a01.w, a23.x, a23.y, a23.z, a23.w};
            #pragma unroll
            for (int m = 0; m < 8; m++) {
                unsigned long long aa = pk2(am[m], am[m]);
                ffma2(acc[m][0], aa, b01.x);
                ffma2(acc[m][1], aa, b01.y);
                ffma2(acc[m][2], aa, b23.x);
                ffma2(acc[m][3], aa, b23.y);
            }
        }
    }

    float bb[8];
    #pragma unroll
    for (int i = 0; i < 8; i++) bb[i] = bias[n0 + tx * 8 + i];
    #pragma unroll
    for (int m = 0; m < 8; m++) {
        float c[8];
        upk2(acc[m][0], c[0], c[1]);
        upk2(acc[m][1], c[2], c[3]);
        upk2(acc[m][2], c[4], c[5]);
        upk2(acc[m][3], c[6], c[7]);
        #pragma unroll
        for (int i = 0; i < 8; i++) c[i] += bb[i];
        float* op = g_xw + (size_t)(m0 + ty * 8 + m) * G_DIM + n0 + tx * 8;
        *(float4*)op       = make_float4(c[0], c[1], c[2], c[3]);
        *(float4*)(op + 4) = make_float4(c[4], c[5], c[6], c[7]);
    }
}

// =====================================================================
// Kernel 2: persistent LSTM recurrence. Grid (32, 4) = 128 CTAs, 256 thr.
// CTA (j, bq) owns batches [bq*16, bq*16+16) and h-columns [j*16, j*16+16).
// U slice [512][64] resident in smem; h tile [16][512] reloaded per step (ld.cg).
// Distributed-flag global barrier between steps.
// =====================================================================
#define SMEM_FLOATS (512 * 64 + 16 * 520 + 16 * 64)
#define SMEM_BYTES  (SMEM_FLOATS * 4)

__global__ void lstm_rec_kernel(const float* __restrict__ U,
                                float* __restrict__ out, size_t out_size)
{
    extern __shared__ float sm[];
    float* U_s    = sm;                  // [512][64]
    float* h_s    = sm + 512 * 64;       // [16][520]  (pad 8 -> conflict-free, 16B-aligned)
    float* gate_s = h_s + 16 * 520;      // [16][64]  layout [b][q*16 + hc]

    const int t   = threadIdx.x;
    const int g   = t & 15;              // col-group (4 gate cols) for compute phase
    const int b   = t >> 4;              // local batch for compute phase
    const int j   = blockIdx.x;          // 0..31 column slice
    const int bq  = blockIdx.y;          // 0..3 batch slice
    const int cta = blockIdx.y * 32 + blockIdx.x;   // 0..127

    // ---- load U slice into smem: col (q*16+hc) <- U[k][q*512 + j*16 + hc]
    for (int idx = t; idx < 8192; idx += 256) {
        int k  = idx >> 4;
        int c4 = idx & 15;
        int q4 = c4 >> 2;
        int h4 = (c4 & 3) * 4;
        float4 v = *(const float4*)(U + (size_t)k * G_DIM + q4 * H_DIM + j * 16 + h4);
        *(float4*)&U_s[k * 64 + q4 * 16 + h4] = v;
    }

    // ---- zero h_buf[0] (each CTA zeros its 256-element share)
    g_h[0][cta * 256 + t] = 0.0f;
    float c_reg = 0.0f;

    // barrier base: flags are cumulative across graph replays; all equal at entry.
    unsigned long long base = *((volatile unsigned long long*)&g_flags[cta * 16]);

    // barrier #1: h zero-init visible everywhere
    __threadfence();
    __syncthreads();
    if (t == 0) *((volatile unsigned long long*)&g_flags[cta * 16]) = base + 1;
    if (t < 128) {
        volatile unsigned long long* f = &g_flags[t * 16];
        while (*f < base + 1) __nanosleep(32);
    }
    __syncthreads();
    __threadfence();

    const int q       = g >> 2;
    const int colbase = j * 16;
    const int hc      = t & 15;          // eltwise mapping
    const int b2      = t >> 4;
    const int gb2     = bq * 16 + b2;

    for (int ts = 0; ts < S_LEN; ts++) {
        const int cur = ts & 1, nxt = cur ^ 1;

        // ---- load h tile (this CTA's 16 batches, full 512 cols) via L2 (ld.cg)
        const float* hb = g_h[cur] + (size_t)bq * 16 * H_DIM;
        for (int i = t; i < 2048; i += 256) {
            int bb = i >> 7;
            int k4 = (i & 127) * 4;
            float4 v = __ldcg((const float4*)(hb + bb * H_DIM + k4));
            *(float4*)&h_s[bb * 520 + k4] = v;
        }
        // prefetch the xW term for this thread's 4 gate columns
        const float* xwp = g_xw + ((size_t)ts * B_DIM + bq * 16 + b) * G_DIM
                         + q * H_DIM + colbase + (g & 3) * 4;
        float4 xv = *(const float4*)xwp;
        __syncthreads();

        // ---- gates = xW_t + h @ U  (f32x2 packed FMA)
        unsigned long long a0 = pk2(xv.x, xv.y);
        unsigned long long a1 = pk2(xv.z, xv.w);
        const float* hrow = h_s + b * 520;
        const float* ucol = U_s + g * 4;
        #pragma unroll 8
        for (int k = 0; k < 512; k++) {
            float hv = hrow[k];
            unsigned long long hh = pk2(hv, hv);
            ulonglong2 uv = *(const ulonglong2*)(ucol + (size_t)k * 64);
            ffma2(a0, hh, uv.x);
            ffma2(a1, hh, uv.y);
        }
        float v0, v1, v2, v3;
        upk2(a0, v0, v1);
        upk2(a1, v2, v3);
        if (q == 2) {  // g gate: tanh
            v0 = tanhf(v0); v1 = tanhf(v1); v2 = tanhf(v2); v3 = tanhf(v3);
        } else {       // i, f, o gates: sigmoid
            v0 = sigmoidf_fast(v0); v1 = sigmoidf_fast(v1);
            v2 = sigmoidf_fast(v2); v3 = sigmoidf_fast(v3);
        }
        *(float4*)&gate_s[b * 64 + g * 4] = make_float4(v0, v1, v2, v3);
        __syncthreads();

        // ---- elementwise LSTM cell update; thread owns fixed (b2, hc)
        float iv = gate_s[b2 * 64 +      hc];
        float fv = gate_s[b2 * 64 + 16 + hc];
        float gv = gate_s[b2 * 64 + 32 + hc];
        float ov = gate_s[b2 * 64 + 48 + hc];
        c_reg = fv * c_reg + iv * gv;
        float hval = ov * tanhf(c_reg);
        int col = colbase + hc;
        __stcg(&g_h[nxt][gb2 * H_DIM + col], hval);
        out[(size_t)ts * (B_DIM * H_DIM) + gb2 * H_DIM + col] = hval;

        if (ts < S_LEN - 1) {
            // ---- grid-wide barrier (distributed flags)
            unsigned long long tgt = base + 2 + (unsigned long long)ts;
            __threadfence();
            __syncthreads();
            if (t == 0) *((volatile unsigned long long*)&g_flags[cta * 16]) = tgt;
            if (t < 128) {
                volatile unsigned long long* f = &g_flags[t * 16];
                while (*f < tgt) __nanosleep(32);
            }
            __syncthreads();
            __threadfence();
        } else {
            // final (h_T, c_T) tails if the output buffer includes them
            const size_t SEQ  = (size_t)S_LEN * B_DIM * H_DIM;
            const size_t need = SEQ + 2 * (size_t)B_DIM * H_DIM;
            if (out_size >= need) {
                out[SEQ + gb2 * H_DIM + col]                         = hval;
                out[SEQ + (size_t)B_DIM * H_DIM + gb2 * H_DIM + col] = c_reg;
            }
        }
    }
}

// =====================================================================
extern "C" void kernel_launch(void* const* d_in, const int* in_sizes, int n_in,
                              void* d_out, int out_size) {
    const float* x    = (const float*)d_in[0];
    const float* W    = (const float*)d_in[1];
    const float* U    = (const float*)d_in[2];
    const float* bias = (const float*)d_in[3];
    float* out = (float*)d_out;
    (void)in_sizes; (void)n_in;

    cudaFuncSetAttribute(lstm_rec_kernel,
                         cudaFuncAttributeMaxDynamicSharedMemorySize, SMEM_BYTES);

    dim3 ggrid(G_DIM / 128, (S_LEN * B_DIM) / 128);  // (16, 1024)
    gemm_xw_kernel<<<ggrid, 256>>>(x, W, bias);

    dim3 rgrid(32, 4);  // 128 CTAs, 1 per SM (smem-limited) -> safe spin barrier
    lstm_rec_kernel<<<rgrid, 256, SMEM_BYTES>>>(U, out, (size_t)out_size);
}

// round 3
// speedup vs baseline: 1.1622x; 1.1622x over previous
#include <cuda_runtime.h>
#include <cstdint>
#include <cstddef>

#define S_LEN 2048
#define B_DIM 64
#define I_DIM 512
#define H_DIM 512
#define G_DIM 2048  // 4*H

// ---------------- scratch (static device globals: allocation-free) -------------
__device__ __align__(16) float g_xw[(size_t)S_LEN * B_DIM * G_DIM];   // 1 GB
__device__ __align__(16) float g_h[2][B_DIM * H_DIM];
__device__ unsigned long long g_flags[128 * 16];   // per-CTA flags, 128B apart

// ---------------- packed f32x2 helpers -----------------------------------------
__device__ __forceinline__ unsigned long long pk2(float lo, float hi) {
    unsigned long long r;
    asm("mov.b64 %0, {%1, %2};" : "=l"(r) : "f"(lo), "f"(hi));
    return r;
}
__device__ __forceinline__ void upk2(unsigned long long v, float& lo, float& hi) {
    asm("mov.b64 {%0, %1}, %2;" : "=f"(lo), "=f"(hi) : "l"(v));
}
__device__ __forceinline__ void ffma2(unsigned long long& d, unsigned long long a, unsigned long long b) {
    asm("fma.rn.f32x2 %0, %1, %2, %0;" : "+l"(d) : "l"(a), "l"(b));
}
__device__ __forceinline__ float sigmoidf_fast(float x) {
    return 1.0f / (1.0f + __expf(-x));
}

// =====================================================================
// Kernel 1: xW = x @ W + bias (unchanged from R2 passing version)
// =====================================================================
__global__ __launch_bounds__(256, 2) void gemm_xw_kernel(
    const float* __restrict__ x, const float* __restrict__ W,
    const float* __restrict__ bias)
{
    __shared__ float As[8][128];
    __shared__ float Bs[8][128];

    const int t  = threadIdx.x;
    const int m0 = blockIdx.y * 128;
    const int n0 = blockIdx.x * 128;
    const int tx = t & 15;
    const int ty = t >> 4;

    const int arow = t >> 1, akc = (t & 1) * 4;
    const int brow = t >> 5, bnc = (t & 31) * 4;

    unsigned long long acc[8][4];
    #pragma unroll
    for (int m = 0; m < 8; m++)
        #pragma unroll
        for (int n = 0; n < 4; n++) acc[m][n] = 0ULL;

    float4 av = *(const float4*)(x + (size_t)(m0 + arow) * I_DIM + akc);
    float4 bv = *(const float4*)(W + (size_t)brow * G_DIM + n0 + bnc);

    for (int kt = 0; kt < 64; kt++) {
        __syncthreads();
        As[akc + 0][arow] = av.x;
        As[akc + 1][arow] = av.y;
        As[akc + 2][arow] = av.z;
        As[akc + 3][arow] = av.w;
        *(float4*)&Bs[brow][bnc] = bv;
        __syncthreads();
        if (kt < 63) {
            av = *(const float4*)(x + (size_t)(m0 + arow) * I_DIM + (kt + 1) * 8 + akc);
            bv = *(const float4*)(W + (size_t)((kt + 1) * 8 + brow) * G_DIM + n0 + bnc);
        }
        #pragma unroll
        for (int kk = 0; kk < 8; kk++) {
            float4 a01 = *(const float4*)&As[kk][ty * 8];
            float4 a23 = *(const float4*)&As[kk][ty * 8 + 4];
            ulonglong2 b01 = *(const ulonglong2*)&Bs[kk][tx * 8];
            ulonglong2 b23 = *(const ulonglong2*)&Bs[kk][tx * 8 + 4];
            float am[8] = {a01.x, a01.y, a01.z, a01.w, a23.x, a23.y, a23.z, a23.w};
            #pragma unroll
            for (int m = 0; m < 8; m++) {
                unsigned long long aa = pk2(am[m], am[m]);
                ffma2(acc[m][0], aa, b01.x);
                ffma2(acc[m][1], aa, b01.y);
                ffma2(acc[m][2], aa, b23.x);
                ffma2(acc[m][3], aa, b23.y);
            }
        }
    }

    float bb[8];
    #pragma unroll
    for (int i = 0; i < 8; i++) bb[i] = bias[n0 + tx * 8 + i];
    #pragma unroll
    for (int m = 0; m < 8; m++) {
        float c[8];
        upk2(acc[m][0], c[0], c[1]);
        upk2(acc[m][1], c[2], c[3]);
        upk2(acc[m][2], c[4], c[5]);
        upk2(acc[m][3], c[6], c[7]);
        #pragma unroll
        for (int i = 0; i < 8; i++) c[i] += bb[i];
        float* op = g_xw + (size_t)(m0 + ty * 8 + m) * G_DIM + n0 + tx * 8;
        *(float4*)op       = make_float4(c[0], c[1], c[2], c[3]);
        *(float4*)(op + 4) = make_float4(c[4], c[5], c[6], c[7]);
    }
}

// =====================================================================
// Kernel 2: persistent recurrence, k-packed f32x2.
// Grid (64, 2) = 128 CTAs. CTA (j, bq): batches [bq*32, bq*32+32),
// gate-cols c in [0,32): global gc = (c>>3)*512 + j*8 + (c&7).
// Layouts: U_s[kq][32 cols][4 k]  pitch 128 floats,
//          h_s[kq][32 batch][4 k] pitch 132 floats (conflict-free pad).
// Thread tile 2b x 2c, warp shaped 4(tx) x 8(ty) for 4 crossbar phases/kq.
// =====================================================================
#define NQ     128                       // k-quads
#define UPITCH 128                       // floats per kq row (U)
#define HPITCH 132                       // floats per kq row (h, padded)
#define GPITCH 33                        // gate_s row pitch
#define SMEM_FLOATS (NQ * UPITCH + NQ * HPITCH + 32 * GPITCH)
#define SMEM_BYTES  (SMEM_FLOATS * 4)

__global__ void lstm_rec_kernel(const float* __restrict__ U,
                                float* __restrict__ out, size_t out_size)
{
    extern __shared__ float sm[];
    float* U_s    = sm;                       // [128][128]
    float* h_s    = sm + NQ * UPITCH;         // [128][132]
    float* gate_s = h_s + NQ * HPITCH;        // [32][33]

    const int t   = threadIdx.x;
    const int j   = blockIdx.x;               // 0..63 col slice (8 h-cols)
    const int bq  = blockIdx.y;               // 0..1 batch half
    const int cta = bq * 64 + j;              // 0..127

    // warp-internal 4x8 shape: tx = b0b1|b5b6, ty = b2b3b4|b7
    const int tx = (t & 3) | ((t >> 3) & 0xC);      // 0..15 (col pair base)
    const int ty = ((t >> 2) & 7) | ((t >> 4) & 8); // 0..15 (batch pair base)

    // ---- load U slice: U_s[kq][c][ki] <- U[kq*4+ki][gc(c)]
    for (int idx = t; idx < 512 * 32; idx += 256) {
        int k = idx >> 5;
        int c = idx & 31;
        float v = U[(size_t)k * G_DIM + (c >> 3) * H_DIM + j * 8 + (c & 7)];
        U_s[(k >> 2) * UPITCH + c * 4 + (k & 3)] = v;
    }

    // ---- zero h_buf[0]
    g_h[0][cta * 256 + t] = 0.0f;
    float c_reg = 0.0f;

    unsigned long long base = *((volatile unsigned long long*)&g_flags[cta * 16]);

    __threadfence();
    __syncthreads();
    if (t == 0) *((volatile unsigned long long*)&g_flags[cta * 16]) = base + 1;
    if (t < 128) {
        volatile unsigned long long* f = &g_flags[t * 16];
        while (*f < base + 1) {}
    }
    __syncthreads();
    __threadfence();

    const int b2 = t >> 3;              // eltwise: batch 0..31
    const int hc = t & 7;               // eltwise: h-col 0..7
    const int gb = bq * 32 + b2;        // global batch
    const int col = j * 8 + hc;         // global h col

    const int gc00 = (tx >> 3) * H_DIM + j * 8 + (tx & 7);   // gate col of c=tx

    for (int ts = 0; ts < S_LEN; ts++) {
        const int cur = ts & 1, nxt = cur ^ 1;

        // ---- prefetch xW terms for this thread's 4 outputs
        const float* xwb = g_xw + ((size_t)ts * B_DIM + bq * 32 + ty) * G_DIM + gc00;
        float xw00 = xwb[0];
        float xw01 = xwb[1024];                   // c = tx+16
        float xw10 = xwb[16 * G_DIM];             // b = ty+16
        float xw11 = xwb[16 * G_DIM + 1024];

        // ---- load h tile (32 batches x 512) coalesced -> padded smem
        {
            const float* hb = g_h[cur] + (size_t)bq * 32 * H_DIM;
            #pragma unroll
            for (int n = 0; n < 16; n++) {
                int idx = n * 256 + t;
                int b  = idx >> 7;            // 0..31
                int kq = idx & 127;           // 0..127
                float4 v = __ldcg((const float4*)(hb + b * H_DIM + kq * 4));
                *(float4*)&h_s[kq * HPITCH + b * 4] = v;
            }
        }
        __syncthreads();

        // ---- gates = h @ U  (k-packed f32x2, 2b x 2c per thread)
        unsigned long long a00 = 0ULL, a01 = 0ULL, a10 = 0ULL, a11 = 0ULL;
        const char* up = (const char*)(U_s + tx * 4);
        const char* hp = (const char*)(h_s + ty * 4);
        #pragma unroll 4
        for (int kq = 0; kq < NQ; kq++) {
            ulonglong2 u0 = *(const ulonglong2*)(up);
            ulonglong2 u1 = *(const ulonglong2*)(up + 16 * 16);       // c = tx+16
            ulonglong2 h0 = *(const ulonglong2*)(hp);
            ulonglong2 h1 = *(const ulonglong2*)(hp + 16 * 16);       // b = ty+16
            ffma2(a00, h0.x, u0.x); ffma2(a00, h0.y, u0.y);
            ffma2(a01, h0.x, u1.x); ffma2(a01, h0.y, u1.y);
            ffma2(a10, h1.x, u0.x); ffma2(a10, h1.y, u0.y);
            ffma2(a11, h1.x, u1.x); ffma2(a11, h1.y, u1.y);
            up += UPITCH * 4;
            hp += HPITCH * 4;
        }
        float l, h_;
        float s00, s01, s10, s11;
        upk2(a00, l, h_); s00 = l + h_ + xw00;
        upk2(a01, l, h_); s01 = l + h_ + xw01;
        upk2(a10, l, h_); s10 = l + h_ + xw10;
        upk2(a11, l, h_); s11 = l + h_ + xw11;

        // activations: c=tx in [0,16) -> gates i/f (sigmoid);
        // c=tx+16: tx<8 -> g (tanh), tx>=8 -> o (sigmoid)
        s00 = sigmoidf_fast(s00);
        s10 = sigmoidf_fast(s10);
        if (tx < 8) { s01 = tanhf(s01); s11 = tanhf(s11); }
        else        { s01 = sigmoidf_fast(s01); s11 = sigmoidf_fast(s11); }

        gate_s[ty * GPITCH + tx]               = s00;
        gate_s[ty * GPITCH + tx + 16]          = s01;
        gate_s[(ty + 16) * GPITCH + tx]        = s10;
        gate_s[(ty + 16) * GPITCH + tx + 16]   = s11;
        __syncthreads();

        // ---- eltwise cell update: thread owns (b2, hc)
        float iv = gate_s[b2 * GPITCH +      hc];
        float fv = gate_s[b2 * GPITCH +  8 + hc];
        float gv = gate_s[b2 * GPITCH + 16 + hc];
        float ov = gate_s[b2 * GPITCH + 24 + hc];
        c_reg = fv * c_reg + iv * gv;
        float hval = ov * tanhf(c_reg);
        __stcg(&g_h[nxt][gb * H_DIM + col], hval);
        out[(size_t)ts * (B_DIM * H_DIM) + gb * H_DIM + col] = hval;

        if (ts < S_LEN - 1) {
            unsigned long long tgt = base + 2 + (unsigned long long)ts;
            __threadfence();
            __syncthreads();
            if (t == 0) *((volatile unsigned long long*)&g_flags[cta * 16]) = tgt;
            if (t < 128) {
                volatile unsigned long long* f = &g_flags[t * 16];
                while (*f < tgt) {}
            }
            __syncthreads();
            __threadfence();
        } else {
            const size_t SEQ  = (size_t)S_LEN * B_DIM * H_DIM;
            const size_t need = SEQ + 2 * (size_t)B_DIM * H_DIM;
            if (out_size >= need) {
                out[SEQ + gb * H_DIM + col]                          = hval;
                out[SEQ + (size_t)B_DIM * H_DIM + gb * H_DIM + col]  = c_reg;
            }
        }
    }
}

// =====================================================================
extern "C" void kernel_launch(void* const* d_in, const int* in_sizes, int n_in,
                              void* d_out, int out_size) {
    const float* x    = (const float*)d_in[0];
    const float* W    = (const float*)d_in[1];
    const float* U    = (const float*)d_in[2];
    const float* bias = (const float*)d_in[3];
    float* out = (float*)d_out;
    (void)in_sizes; (void)n_in;

    cudaFuncSetAttribute(lstm_rec_kernel,
                         cudaFuncAttributeMaxDynamicSharedMemorySize, SMEM_BYTES);

    dim3 ggrid(G_DIM / 128, (S_LEN * B_DIM) / 128);  // (16, 1024)
    gemm_xw_kernel<<<ggrid, 256>>>(x, W, bias);

    dim3 rgrid(64, 2);  // 128 CTAs, 1 per SM (smem-limited)
    lstm_rec_kernel<<<rgrid, 256, SMEM_BYTES>>>(U, out, (size_t)out_size);
}

// round 4
// speedup vs baseline: 1.3812x; 1.1885x over previous
#include <cuda_runtime.h>
#include <cstdint>
#include <cstddef>

#define S_LEN 2048
#define B_DIM 64
#define I_DIM 512
#define H_DIM 512
#define G_DIM 2048  // 4*H

// ---------------- scratch (static device globals) -------------------------------
__device__ __align__(16) float g_xw[(size_t)S_LEN * B_DIM * G_DIM];   // 1 GB
__device__ __align__(16) float g_h[2][B_DIM * H_DIM];
__device__ __align__(16) unsigned long long g_flags[128 * 16];  // 128B-strided flags

// ---------------- packed f32x2 helpers ------------------------------------------
__device__ __forceinline__ unsigned long long pk2(float lo, float hi) {
    unsigned long long r;
    asm("mov.b64 %0, {%1, %2};" : "=l"(r) : "f"(lo), "f"(hi));
    return r;
}
__device__ __forceinline__ void upk2(unsigned long long v, float& lo, float& hi) {
    asm("mov.b64 {%0, %1}, %2;" : "=f"(lo), "=f"(hi) : "l"(v));
}
__device__ __forceinline__ void ffma2(unsigned long long& d, unsigned long long a, unsigned long long b) {
    asm("fma.rn.f32x2 %0, %1, %2, %0;" : "+l"(d) : "l"(a), "l"(b));
}
__device__ __forceinline__ float sigmoidf_fast(float x) {
    return 1.0f / (1.0f + __expf(-x));
}
// ---------------- release/acquire flag ops (no membar.gl) ------------------------
__device__ __forceinline__ void st_release_gpu(unsigned long long* p, unsigned long long v) {
    asm volatile("st.release.gpu.u64 [%0], %1;" :: "l"(p), "l"(v) : "memory");
}
__device__ __forceinline__ unsigned long long ld_acquire_gpu(const unsigned long long* p) {
    unsigned long long v;
    asm volatile("ld.acquire.gpu.u64 %0, [%1];" : "=l"(v) : "l"(p) : "memory");
    return v;
}

// =====================================================================
// Kernel 1: xW = x @ W + bias (unchanged — near its f32x2 issue floor)
// =====================================================================
__global__ __launch_bounds__(256, 2) void gemm_xw_kernel(
    const float* __restrict__ x, const float* __restrict__ W,
    const float* __restrict__ bias)
{
    __shared__ float As[8][128];
    __shared__ float Bs[8][128];

    const int t  = threadIdx.x;
    const int m0 = blockIdx.y * 128;
    const int n0 = blockIdx.x * 128;
    const int tx = t & 15;
    const int ty = t >> 4;

    const int arow = t >> 1, akc = (t & 1) * 4;
    const int brow = t >> 5, bnc = (t & 31) * 4;

    unsigned long long acc[8][4];
    #pragma unroll
    for (int m = 0; m < 8; m++)
        #pragma unroll
        for (int n = 0; n < 4; n++) acc[m][n] = 0ULL;

    float4 av = *(const float4*)(x + (size_t)(m0 + arow) * I_DIM + akc);
    float4 bv = *(const float4*)(W + (size_t)brow * G_DIM + n0 + bnc);

    for (int kt = 0; kt < 64; kt++) {
        __syncthreads();
        As[akc + 0][arow] = av.x;
        As[akc + 1][arow] = av.y;
        As[akc + 2][arow] = av.z;
        As[akc + 3][arow] = av.w;
        *(float4*)&Bs[brow][bnc] = bv;
        __syncthreads();
        if (kt < 63) {
            av = *(const float4*)(x + (size_t)(m0 + arow) * I_DIM + (kt + 1) * 8 + akc);
            bv = *(const float4*)(W + (size_t)((kt + 1) * 8 + brow) * G_DIM + n0 + bnc);
        }
        #pragma unroll
        for (int kk = 0; kk < 8; kk++) {
            float4 a01 = *(const float4*)&As[kk][ty * 8];
            float4 a23 = *(const float4*)&As[kk][ty * 8 + 4];
            ulonglong2 b01 = *(const ulonglong2*)&Bs[kk][tx * 8];
            ulonglong2 b23 = *(const ulonglong2*)&Bs[kk][tx * 8 + 4];
            float am[8] = {a01.x, a01.y, a01.z, a01.w, a23.x, a23.y, a23.z, a23.w};
            #pragma unroll
            for (int m = 0; m < 8; m++) {
                unsigned long long aa = pk2(am[m], am[m]);
                ffma2(acc[m][0], aa, b01.x);
                ffma2(acc[m][1], aa, b01.y);
                ffma2(acc[m][2], aa, b23.x);
                ffma2(acc[m][3], aa, b23.y);
            }
        }
    }

    float bb[8];
    #pragma unroll
    for (int i = 0; i < 8; i++) bb[i] = bias[n0 + tx * 8 + i];
    #pragma unroll
    for (int m = 0; m < 8; m++) {
        float c[8];
        upk2(acc[m][0], c[0], c[1]);
        upk2(acc[m][1], c[2], c[3]);
        upk2(acc[m][2], c[4], c[5]);
        upk2(acc[m][3], c[6], c[7]);
        #pragma unroll
        for (int i = 0; i < 8; i++) c[i] += bb[i];
        float* op = g_xw + (size_t)(m0 + ty * 8 + m) * G_DIM + n0 + tx * 8;
        *(float4*)op       = make_float4(c[0], c[1], c[2], c[3]);
        *(float4*)(op + 4) = make_float4(c[4], c[5], c[6], c[7]);
    }
}

// =====================================================================
// Kernel 2: persistent recurrence, 128 threads/CTA, 2c x 4b thread tile.
// Grid (64, 2) = 128 CTAs. CTA (j,bq): batches [bq*32,+32), 32 gate cols:
// CTA col c -> global gate col (c>>3)*512 + j*8 + (c&7).
// U_s[kq][32c][4k] pitch 128; h_s[kq][32b][4k] pitch 132; gate_s[32][33].
// =====================================================================
#define NQ     128
#define UPITCH 128
#define HPITCH 132
#define GPITCH 33
#define SMEM_FLOATS (NQ * UPITCH + NQ * HPITCH + 32 * GPITCH)
#define SMEM_BYTES  (SMEM_FLOATS * 4)

__global__ __launch_bounds__(128, 1) void lstm_rec_kernel(
    const float* __restrict__ U, float* __restrict__ out, size_t out_size)
{
    extern __shared__ float sm[];
    float* U_s    = sm;                       // [128][128]
    float* h_s    = sm + NQ * UPITCH;         // [128][132]
    float* gate_s = h_s + NQ * HPITCH;        // [32][33]

    const int t   = threadIdx.x;              // 0..127
    const int j   = blockIdx.x;               // 0..63
    const int bq  = blockIdx.y;               // 0..1
    const int cta = bq * 64 + j;              // 0..127

    const int tx = t & 15;                    // col: c0=tx, c1=tx+16
    const int ty = t >> 4;                    // batch quad: b = ty*4+i

    // ---- U slice load: U_s[kq][c][ki] <- U[k][(c>>3)*512 + j*8 + (c&7)]
    for (int idx = t; idx < 512 * 32; idx += 128) {
        int k = idx >> 5;
        int c = idx & 31;
        float v = U[(size_t)k * G_DIM + (c >> 3) * H_DIM + j * 8 + (c & 7)];
        U_s[(k >> 2) * UPITCH + c * 4 + (k & 3)] = v;
    }

    // ---- zero h_buf[0] (each CTA zeros its 256-float share)
    g_h[0][cta * 256 + t]       = 0.0f;
    g_h[0][cta * 256 + 128 + t] = 0.0f;

    unsigned long long base = ld_acquire_gpu(&g_flags[cta * 16]);

    // init barrier (CG grid.sync pattern)
    __syncthreads();
    if (t == 0) st_release_gpu(&g_flags[cta * 16], base + 1);
    {
        const unsigned long long* f = &g_flags[t * 16];
        while (ld_acquire_gpu(f) < base + 1) {}
    }
    __syncthreads();

    // eltwise ownership: cells (b2, hc) and (b2+16, hc)
    const int hc  = t & 7;
    const int b2  = t >> 3;                   // 0..15
    const int col = j * 8 + hc;
    const int gbA = bq * 32 + b2;
    const int gbB = gbA + 16;
    float cA = 0.0f, cB = 0.0f;

    const int gc0 = (tx >> 3) * H_DIM + j * 8 + (tx & 7);   // global col of c0

    for (int ts = 0; ts < S_LEN; ts++) {
        const int cur = ts & 1, nxt = cur ^ 1;

        // ---- xW prefetch FIRST (independent of barrier; hides DRAM latency)
        float xw0[4], xw1[4];
        {
            const float* xb = g_xw + ((size_t)ts * B_DIM + bq * 32 + ty * 4) * G_DIM + gc0;
            #pragma unroll
            for (int i = 0; i < 4; i++) {
                xw0[i] = __ldcs(xb + (size_t)i * G_DIM);
                xw1[i] = __ldcs(xb + (size_t)i * G_DIM + 1024);
            }
        }

        // ---- wait for previous step's h (skip at ts=0: init barrier covered it)
        if (ts > 0) {
            unsigned long long tgt = base + 1 + (unsigned long long)ts;
            const unsigned long long* f = &g_flags[t * 16];
            while (ld_acquire_gpu(f) < tgt) {}
            __syncthreads();
        }

        // ---- h tile load: iter n loads batch n, thread t -> k-quad t
        {
            const float* hb = g_h[cur] + (size_t)bq * 32 * H_DIM;
            #pragma unroll 8
            for (int n = 0; n < 32; n++) {
                float4 v = __ldcg((const float4*)(hb + n * H_DIM + t * 4));
                *(float4*)&h_s[t * HPITCH + n * 4] = v;
            }
        }
        __syncthreads();

        // ---- gates = h @ U (k-packed f32x2; 2 cols x 4 batches per thread)
        unsigned long long a0[4], a1[4];
        #pragma unroll
        for (int i = 0; i < 4; i++) { a0[i] = 0ULL; a1[i] = 0ULL; }

        const char* up = (const char*)(U_s + tx * 4);
        const char* hp = (const char*)(h_s + ty * 16);
        #pragma unroll 4
        for (int kq = 0; kq < NQ; kq++) {
            ulonglong2 u0 = *(const ulonglong2*)(up);
            ulonglong2 u1 = *(const ulonglong2*)(up + 16 * 16);   // c1 = tx+16
            ulonglong2 h0 = *(const ulonglong2*)(hp);
            ulonglong2 h1 = *(const ulonglong2*)(hp + 16);
            ulonglong2 h2 = *(const ulonglong2*)(hp + 32);
            ulonglong2 h3 = *(const ulonglong2*)(hp + 48);
            ffma2(a0[0], h0.x, u0.x); ffma2(a0[0], h0.y, u0.y);
            ffma2(a0[1], h1.x, u0.x); ffma2(a0[1], h1.y, u0.y);
            ffma2(a0[2], h2.x, u0.x); ffma2(a0[2], h2.y, u0.y);
            ffma2(a0[3], h3.x, u0.x); ffma2(a0[3], h3.y, u0.y);
            ffma2(a1[0], h0.x, u1.x); ffma2(a1[0], h0.y, u1.y);
            ffma2(a1[1], h1.x, u1.x); ffma2(a1[1], h1.y, u1.y);
            ffma2(a1[2], h2.x, u1.x); ffma2(a1[2], h2.y, u1.y);
            ffma2(a1[3], h3.x, u1.x); ffma2(a1[3], h3.y, u1.y);
            up += UPITCH * 4;
            hp += HPITCH * 4;
        }

        // ---- activations + gate exchange
        #pragma unroll
        for (int i = 0; i < 4; i++) {
            float l, h_;
            upk2(a0[i], l, h_);
            float s0 = sigmoidf_fast(l + h_ + xw0[i]);        // c0: i or f gate
            upk2(a1[i], l, h_);
            float s1v = l + h_ + xw1[i];                      // c1: g or o gate
            float s1 = (tx < 8) ? tanhf(s1v) : sigmoidf_fast(s1v);
            gate_s[(ty * 4 + i) * GPITCH + tx]      = s0;
            gate_s[(ty * 4 + i) * GPITCH + tx + 16] = s1;
        }
        __syncthreads();

        // ---- eltwise cell update (2 cells per thread), early h store
        {
            float iv = gate_s[b2 * GPITCH +      hc];
            float fv = gate_s[b2 * GPITCH +  8 + hc];
            float gv = gate_s[b2 * GPITCH + 16 + hc];
            float ov = gate_s[b2 * GPITCH + 24 + hc];
            cA = fv * cA + iv * gv;
            float hA = ov * tanhf(cA);

            float iv2 = gate_s[(b2 + 16) * GPITCH +      hc];
            float fv2 = gate_s[(b2 + 16) * GPITCH +  8 + hc];
            float gv2 = gate_s[(b2 + 16) * GPITCH + 16 + hc];
            float ov2 = gate_s[(b2 + 16) * GPITCH + 24 + hc];
            cB = fv2 * cB + iv2 * gv2;
            float hB = ov2 * tanhf(cB);

            __stcg(&g_h[nxt][gbA * H_DIM + col], hA);
            __stcg(&g_h[nxt][gbB * H_DIM + col], hB);

            float* ob = out + (size_t)ts * (B_DIM * H_DIM);
            __stcs(&ob[gbA * H_DIM + col], hA);
            __stcs(&ob[gbB * H_DIM + col], hB);

            if (ts == S_LEN - 1) {
                const size_t SEQ  = (size_t)S_LEN * B_DIM * H_DIM;
                const size_t need = SEQ + 2 * (size_t)B_DIM * H_DIM;
                if (out_size >= need) {
                    out[SEQ + gbA * H_DIM + col]                         = hA;
                    out[SEQ + gbB * H_DIM + col]                         = hB;
                    out[SEQ + (size_t)B_DIM * H_DIM + gbA * H_DIM + col] = cA;
                    out[SEQ + (size_t)B_DIM * H_DIM + gbB * H_DIM + col] = cB;
                }
            }
        }

        // ---- release: h for step ts is done (flag value base+2+ts)
        if (ts < S_LEN - 1) {
            __syncthreads();
            if (t == 0) st_release_gpu(&g_flags[cta * 16], base + 2 + (unsigned long long)ts);
        }
    }
}

// =====================================================================
extern "C" void kernel_launch(void* const* d_in, const int* in_sizes, int n_in,
                              void* d_out, int out_size) {
    const float* x    = (const float*)d_in[0];
    const float* W    = (const float*)d_in[1];
    const float* U    = (const float*)d_in[2];
    const float* bias = (const float*)d_in[3];
    float* out = (float*)d_out;
    (void)in_sizes; (void)n_in;

    cudaFuncSetAttribute(lstm_rec_kernel,
                         cudaFuncAttributeMaxDynamicSharedMemorySize, SMEM_BYTES);

    dim3 ggrid(G_DIM / 128, (S_LEN * B_DIM) / 128);  // (16, 1024)
    gemm_xw_kernel<<<ggrid, 256>>>(x, W, bias);

    dim3 rgrid(64, 2);  // 128 CTAs, 1 per SM (smem-limited) -> all co-resident
    lstm_rec_kernel<<<rgrid, 128, SMEM_BYTES>>>(U, out, (size_t)out_size);
}